// round 2
// baseline (speedup 1.0000x reference)
#include <cuda_runtime.h>

#define BN 16
#define QN 256
#define KN 256
#define DN 256
#define HN 256
#define TQ 16

// scratch (device globals: no allocation allowed)
__device__ float g_qproj[BN * QN * HN];          // [b][q][h]
__device__ float g_kproj[BN * HN * KN];          // [b][h][kj]  (transposed)

__device__ __forceinline__ float fast_tanh(float x) {
    float r;
    asm("tanh.approx.f32 %0, %1;" : "=f"(r) : "f"(x));
    return r;
}

// ---------------------------------------------------------------------------
// Kernel A: dual projection GEMM.
//   z==0:  g_qproj[m][h]          = queries[m][:] @ Wq[:][h]
//   z==1:  g_kproj[b][h][kj]      = keys[m][:]    @ Wk[:][h]   (transposed store)
// m = flat row over B*seq = 4096. Tiles 64x64, BK=16, 256 threads, 4x4/thread.
// ---------------------------------------------------------------------------
__global__ void __launch_bounds__(256) proj_kernel(
    const float* __restrict__ Aq, const float* __restrict__ Ak,
    const float* __restrict__ Wq, const float* __restrict__ Wk)
{
    const int z = blockIdx.z;
    const float* __restrict__ A = z ? Ak : Aq;
    const float* __restrict__ W = z ? Wk : Wq;

    __shared__ float As[16][64];   // [k][m]
    __shared__ float Ws[16][64];   // [k][n]

    const int tid = threadIdx.x;
    const int m0 = blockIdx.x * 64;
    const int n0 = blockIdx.y * 64;
    const int tx = tid & 15, ty = tid >> 4;

    const int ar = tid >> 2, ac4 = tid & 3;     // A tile: 64 rows x 16 cols
    const int wr = tid >> 4, wc4 = tid & 15;    // W tile: 16 rows x 64 cols

    float c[4][4] = {};

    for (int kk = 0; kk < 256; kk += 16) {
        float4 av = *(const float4*)&A[(m0 + ar) * 256 + kk + ac4 * 4];
        As[ac4 * 4 + 0][ar] = av.x;
        As[ac4 * 4 + 1][ar] = av.y;
        As[ac4 * 4 + 2][ar] = av.z;
        As[ac4 * 4 + 3][ar] = av.w;
        *(float4*)&Ws[wr][wc4 * 4] =
            *(const float4*)&W[(kk + wr) * 256 + n0 + wc4 * 4];
        __syncthreads();
#pragma unroll
        for (int k = 0; k < 16; k++) {
            float4 a4 = *(const float4*)&As[k][ty * 4];
            float4 b4 = *(const float4*)&Ws[k][tx * 4];
            float aa[4] = {a4.x, a4.y, a4.z, a4.w};
            float bb[4] = {b4.x, b4.y, b4.z, b4.w};
#pragma unroll
            for (int i = 0; i < 4; i++)
#pragma unroll
                for (int j = 0; j < 4; j++) c[i][j] += aa[i] * bb[j];
        }
        __syncthreads();
    }

    if (z == 0) {
#pragma unroll
        for (int i = 0; i < 4; i++) {
            int m = m0 + ty * 4 + i;
            *(float4*)&g_qproj[m * 256 + n0 + tx * 4] =
                make_float4(c[i][0], c[i][1], c[i][2], c[i][3]);
        }
    } else {
#pragma unroll
        for (int i = 0; i < 4; i++) {
            int m = m0 + ty * 4 + i;
            int b = m >> 8, kj = m & 255;
#pragma unroll
            for (int j = 0; j < 4; j++)
                g_kproj[(b * 256 + n0 + tx * 4 + j) * 256 + kj] = c[i][j];
        }
    }
}

// ---------------------------------------------------------------------------
// Kernel B: fused scores (tanh additive attention) + mask + softmax + attn@V.
// One block per (b, 16 q-rows). 256 threads; score phase: thread == kj column,
// 16 row-accumulators; k chunk in registers, q broadcast from smem (LDS.128).
// MUFU (tanh) is the designed bottleneck.
//
// valid_lens dtype probe: JAX (x64 off) silently makes "int64" into int32.
// Read as int32; if elem[1]==0 the buffer is real int64 (high word of
// vlen[0], which is <=256) -> stride 2 low-word reads. Else int32 -> stride 1.
// In-bounds and deterministic either way.
// ---------------------------------------------------------------------------
__global__ void __launch_bounds__(256, 2) attn_kernel(
    const float* __restrict__ values, const int* __restrict__ vlens_i32,
    const float* __restrict__ wv, float* __restrict__ out)
{
    const int b  = blockIdx.y;
    const int q0 = blockIdx.x * TQ;
    const int tid = threadIdx.x;

    __shared__ float q_s[TQ][HN];     // 16 KB
    __shared__ float s_s[TQ][KN];     // 16 KB (scores -> attn)
    __shared__ float wv_s[HN];

    // load q tile + wv
    const float* qbase = g_qproj + (b * QN + q0) * HN;
    for (int i = tid; i < TQ * HN; i += 256) ((float*)q_s)[i] = qbase[i];
    for (int i = tid; i < HN; i += 256) wv_s[i] = wv[i];
    __syncthreads();

    // ---- score phase: this thread owns column kj = tid ----
    const int kj = tid;
    float acc[TQ];
#pragma unroll
    for (int i = 0; i < TQ; i++) acc[i] = 0.f;

    const float* kbase = g_kproj + b * HN * KN + kj;
#pragma unroll 1
    for (int hc = 0; hc < HN; hc += 16) {
        float kv[16], wr[16];
#pragma unroll
        for (int t = 0; t < 16; t++) kv[t] = __ldg(kbase + (hc + t) * KN);
#pragma unroll
        for (int t = 0; t < 16; t++) wr[t] = wv_s[hc + t];
#pragma unroll
        for (int qi = 0; qi < TQ; qi++) {
            const float4* q4 = (const float4*)&q_s[qi][hc];
#pragma unroll
            for (int t4 = 0; t4 < 4; t4++) {
                float4 qv = q4[t4];
                acc[qi] += wr[t4 * 4 + 0] * fast_tanh(qv.x + kv[t4 * 4 + 0]);
                acc[qi] += wr[t4 * 4 + 1] * fast_tanh(qv.y + kv[t4 * 4 + 1]);
                acc[qi] += wr[t4 * 4 + 2] * fast_tanh(qv.z + kv[t4 * 4 + 2]);
                acc[qi] += wr[t4 * 4 + 3] * fast_tanh(qv.w + kv[t4 * 4 + 3]);
            }
        }
    }

    // ---- mask + stash scores ----
    const int stride = (vlens_i32[1] == 0) ? 2 : 1;   // int64 vs int32 probe
    const int vlen = vlens_i32[b * stride];
    const bool live = (kj < vlen);
#pragma unroll
    for (int qi = 0; qi < TQ; qi++)
        s_s[qi][kj] = live ? acc[qi] : -1e6f;
    __syncthreads();

    // ---- softmax: warp w handles rows 2w, 2w+1 ----
    const int w = tid >> 5, lane = tid & 31;
#pragma unroll
    for (int rr = 0; rr < 2; rr++) {
        const int r = w * 2 + rr;
        float vals[8];
        float vmax = -1e30f;
#pragma unroll
        for (int t = 0; t < 8; t++) {
            vals[t] = s_s[r][lane + t * 32];
            vmax = fmaxf(vmax, vals[t]);
        }
#pragma unroll
        for (int off = 16; off; off >>= 1)
            vmax = fmaxf(vmax, __shfl_xor_sync(0xFFFFFFFFu, vmax, off));
        float vsum = 0.f;
#pragma unroll
        for (int t = 0; t < 8; t++) {
            vals[t] = __expf(vals[t] - vmax);
            vsum += vals[t];
        }
#pragma unroll
        for (int off = 16; off; off >>= 1)
            vsum += __shfl_xor_sync(0xFFFFFFFFu, vsum, off);
        const float inv = 1.f / vsum;
#pragma unroll
        for (int t = 0; t < 8; t++)
            s_s[r][lane + t * 32] = vals[t] * inv;
    }
    __syncthreads();

    // ---- attn @ values: thread owns output column d = tid ----
    const int d = tid;
    const float* vb = values + b * KN * DN + d;
    float o[TQ];
#pragma unroll
    for (int i = 0; i < TQ; i++) o[i] = 0.f;
#pragma unroll 4
    for (int k = 0; k < KN; k++) {
        float v = __ldg(vb + k * DN);
#pragma unroll
        for (int qi = 0; qi < TQ; qi++) o[qi] += s_s[qi][k] * v;
    }
    float* ob = out + (b * QN + q0) * DN + d;
#pragma unroll
    for (int qi = 0; qi < TQ; qi++) ob[qi * DN] = o[qi];
}

// ---------------------------------------------------------------------------
extern "C" void kernel_launch(void* const* d_in, const int* in_sizes, int n_in,
                              void* d_out, int out_size)
{
    const float* queries = (const float*)d_in[0];
    const float* keys    = (const float*)d_in[1];
    const float* values  = (const float*)d_in[2];
    const int*   vlens   = (const int*)d_in[3];
    const float* Wq      = (const float*)d_in[4];
    const float* Wk      = (const float*)d_in[5];
    const float* wv      = (const float*)d_in[6];
    float*       out     = (float*)d_out;

    dim3 gA(64, 4, 2);               // (4096/64, 256/64, {q,k})
    proj_kernel<<<gA, 256>>>(queries, keys, Wq, Wk);

    dim3 gB(QN / TQ, BN);            // (16, 16) = 256 blocks
    attn_kernel<<<gB, 256>>>(values, vlens, wv, out);
}

// round 3
// speedup vs baseline: 1.0146x; 1.0146x over previous
#include <cuda_runtime.h>
#include <cuda_fp16.h>

#define BN 16
#define QN 256
#define KN 256
#define DN 256
#define HN 256
#define TQ 16
#define H2 (HN/2)

// scratch (device globals: no allocation allowed)
__device__ float   g_qproj[BN * QN * HN];        // [b][q][h]      f32
__device__ __half2 g_kproj2[BN * H2 * KN];       // [b][h/2][kj]   half2 (h,h+1)

__device__ __forceinline__ __half2 htanh2(__half2 x) {
    unsigned r, xi = *(unsigned*)&x;
    asm("tanh.approx.f16x2 %0, %1;" : "=r"(r) : "r"(xi));
    return *(__half2*)&r;
}

// ---------------------------------------------------------------------------
// Kernel A: dual projection GEMM.
//   z==0:  g_qproj[m][h]      = queries[m][:] @ Wq[:][h]            (f32)
//   z==1:  g_kproj2[b][h/2][kj] = keys GEMM, transposed + fp16 pack
// Tiles 64x64, BK=16, 256 threads, 4x4/thread.
// ---------------------------------------------------------------------------
__global__ void __launch_bounds__(256) proj_kernel(
    const float* __restrict__ Aq, const float* __restrict__ Ak,
    const float* __restrict__ Wq, const float* __restrict__ Wk)
{
    const int z = blockIdx.z;
    const float* __restrict__ A = z ? Ak : Aq;
    const float* __restrict__ W = z ? Wk : Wq;

    __shared__ float As[16][64];   // [k][m]
    __shared__ float Ws[16][64];   // [k][n]

    const int tid = threadIdx.x;
    const int m0 = blockIdx.x * 64;
    const int n0 = blockIdx.y * 64;
    const int tx = tid & 15, ty = tid >> 4;

    const int ar = tid >> 2, ac4 = tid & 3;     // A tile: 64 rows x 16 cols
    const int wr = tid >> 4, wc4 = tid & 15;    // W tile: 16 rows x 64 cols

    float c[4][4] = {};

    for (int kk = 0; kk < 256; kk += 16) {
        float4 av = *(const float4*)&A[(m0 + ar) * 256 + kk + ac4 * 4];
        As[ac4 * 4 + 0][ar] = av.x;
        As[ac4 * 4 + 1][ar] = av.y;
        As[ac4 * 4 + 2][ar] = av.z;
        As[ac4 * 4 + 3][ar] = av.w;
        *(float4*)&Ws[wr][wc4 * 4] =
            *(const float4*)&W[(kk + wr) * 256 + n0 + wc4 * 4];
        __syncthreads();
#pragma unroll
        for (int k = 0; k < 16; k++) {
            float4 a4 = *(const float4*)&As[k][ty * 4];
            float4 b4 = *(const float4*)&Ws[k][tx * 4];
            float aa[4] = {a4.x, a4.y, a4.z, a4.w};
            float bb[4] = {b4.x, b4.y, b4.z, b4.w};
#pragma unroll
            for (int i = 0; i < 4; i++)
#pragma unroll
                for (int j = 0; j < 4; j++) c[i][j] += aa[i] * bb[j];
        }
        __syncthreads();
    }

    if (z == 0) {
#pragma unroll
        for (int i = 0; i < 4; i++) {
            int m = m0 + ty * 4 + i;
            *(float4*)&g_qproj[m * 256 + n0 + tx * 4] =
                make_float4(c[i][0], c[i][1], c[i][2], c[i][3]);
        }
    } else {
#pragma unroll
        for (int i = 0; i < 4; i++) {
            int m = m0 + ty * 4 + i;
            int b = m >> 8, kj = m & 255;
            int h = n0 + tx * 4;                 // even
            g_kproj2[(b * H2 + (h >> 1) + 0) * KN + kj] =
                __floats2half2_rn(c[i][0], c[i][1]);
            g_kproj2[(b * H2 + (h >> 1) + 1) * KN + kj] =
                __floats2half2_rn(c[i][2], c[i][3]);
        }
    }
}

// ---------------------------------------------------------------------------
// Kernel B: fused scores (fp16x2 tanh additive attention) + mask + softmax
// + attn@V. One block per (b, 16 q-rows); thread == kj column in score phase.
// MUFU work halved vs f32 via tanh.approx.f16x2; fp16 accumulation confined
// to 8-term chunks, promoted to f32 per chunk.
// ---------------------------------------------------------------------------
__global__ void __launch_bounds__(256, 2) attn_kernel(
    const float* __restrict__ values, const int* __restrict__ vlens_i32,
    const float* __restrict__ wv, float* __restrict__ out)
{
    const int b  = blockIdx.y;
    const int q0 = blockIdx.x * TQ;
    const int tid = threadIdx.x;

    __shared__ __half2 q_s2[TQ][H2];   // 8 KB   (q proj, fp16 pairs)
    __shared__ float   s_s[TQ][KN];    // 16 KB  (scores -> attn)
    __shared__ __half2 wv_s2[H2];      // 0.5 KB

    // load q tile (f32 -> half2) + wv
    const float* qbase = g_qproj + (b * QN + q0) * HN;
    for (int i = tid; i < TQ * H2; i += 256) {
        float2 v = ((const float2*)qbase)[i];
        ((__half2*)q_s2)[i] = __float22half2_rn(v);
    }
    for (int i = tid; i < H2; i += 256) {
        float2 v = ((const float2*)wv)[i];
        wv_s2[i] = __float22half2_rn(v);
    }
    __syncthreads();

    // ---- score phase: this thread owns column kj = tid ----
    const int kj = tid;
    float acc[TQ];
#pragma unroll
    for (int i = 0; i < TQ; i++) acc[i] = 0.f;

    const __half2* kbase = g_kproj2 + b * H2 * KN + kj;
#pragma unroll 1
    for (int hc2 = 0; hc2 < H2; hc2 += 4) {          // 8 h-elems per chunk
        __half2 kv2[4], wr2[4];
#pragma unroll
        for (int t = 0; t < 4; t++) kv2[t] = __ldg(kbase + (hc2 + t) * KN);
#pragma unroll
        for (int t = 0; t < 4; t++) wr2[t] = wv_s2[hc2 + t];
#pragma unroll
        for (int qi = 0; qi < TQ; qi++) {
            uint4 qraw = *(const uint4*)&q_s2[qi][hc2];   // 4 half2 = 8 h
            __half2 q2[4];
            q2[0] = *(__half2*)&qraw.x; q2[1] = *(__half2*)&qraw.y;
            q2[2] = *(__half2*)&qraw.z; q2[3] = *(__half2*)&qraw.w;
            __half2 a = __float2half2_rn(0.f);
#pragma unroll
            for (int t = 0; t < 4; t++)
                a = __hfma2(wr2[t], htanh2(__hadd2(q2[t], kv2[t])), a);
            float2 f = __half22float2(a);
            acc[qi] += f.x + f.y;
        }
    }

    // ---- mask + stash scores ----
    const int stride = (vlens_i32[1] == 0) ? 2 : 1;   // int64 vs int32 probe
    const int vlen = vlens_i32[b * stride];
    const bool live = (kj < vlen);
#pragma unroll
    for (int qi = 0; qi < TQ; qi++)
        s_s[qi][kj] = live ? acc[qi] : -1e6f;
    __syncthreads();

    // ---- softmax: warp w handles rows 2w, 2w+1 ----
    const int w = tid >> 5, lane = tid & 31;
#pragma unroll
    for (int rr = 0; rr < 2; rr++) {
        const int r = w * 2 + rr;
        float vals[8];
        float vmax = -1e30f;
#pragma unroll
        for (int t = 0; t < 8; t++) {
            vals[t] = s_s[r][lane + t * 32];
            vmax = fmaxf(vmax, vals[t]);
        }
#pragma unroll
        for (int off = 16; off; off >>= 1)
            vmax = fmaxf(vmax, __shfl_xor_sync(0xFFFFFFFFu, vmax, off));
        float vsum = 0.f;
#pragma unroll
        for (int t = 0; t < 8; t++) {
            vals[t] = __expf(vals[t] - vmax);
            vsum += vals[t];
        }
#pragma unroll
        for (int off = 16; off; off >>= 1)
            vsum += __shfl_xor_sync(0xFFFFFFFFu, vsum, off);
        const float inv = 1.f / vsum;
#pragma unroll
        for (int t = 0; t < 8; t++)
            s_s[r][lane + t * 32] = vals[t] * inv;
    }
    __syncthreads();

    // ---- attn @ values: thread owns output column d = tid ----
    const int d = tid;
    const float* vb = values + b * KN * DN + d;
    float o[TQ];
#pragma unroll
    for (int i = 0; i < TQ; i++) o[i] = 0.f;
#pragma unroll 4
    for (int k = 0; k < KN; k++) {
        float v = __ldg(vb + k * DN);
#pragma unroll
        for (int qi = 0; qi < TQ; qi++) o[qi] += s_s[qi][k] * v;
    }
    float* ob = out + (b * QN + q0) * DN + d;
#pragma unroll
    for (int qi = 0; qi < TQ; qi++) ob[qi * DN] = o[qi];
}

// ---------------------------------------------------------------------------
extern "C" void kernel_launch(void* const* d_in, const int* in_sizes, int n_in,
                              void* d_out, int out_size)
{
    const float* queries = (const float*)d_in[0];
    const float* keys    = (const float*)d_in[1];
    const float* values  = (const float*)d_in[2];
    const int*   vlens   = (const int*)d_in[3];
    const float* Wq      = (const float*)d_in[4];
    const float* Wk      = (const float*)d_in[5];
    const float* wv      = (const float*)d_in[6];
    float*       out     = (float*)d_out;

    dim3 gA(64, 4, 2);               // (4096/64, 256/64, {q,k})
    proj_kernel<<<gA, 256>>>(queries, keys, Wq, Wk);

    dim3 gB(QN / TQ, BN);            // (16, 16) = 256 blocks
    attn_kernel<<<gB, 256>>>(values, vlens, wv, out);
}

// round 5
// speedup vs baseline: 1.0865x; 1.0709x over previous
#include <cuda_runtime.h>
#include <cuda_fp16.h>

#define BN 16
#define QN 256
#define KN 256
#define DN 256
#define HN 256
#define TQ 16
#define H2 (HN/2)

// scratch (device globals: no allocation allowed)
__device__ float   g_qproj[BN * QN * HN];        // [b][q][h]      f32
__device__ __half2 g_kproj2[BN * H2 * KN];       // [b][h/2][kj]   half2 (h,h+1)

__device__ __forceinline__ __half2 htanh2(__half2 x) {
    unsigned r, xi = *(unsigned*)&x;
    asm("tanh.approx.f16x2 %0, %1;" : "=r"(r) : "r"(xi));
    return *(__half2*)&r;
}

// ---------------------------------------------------------------------------
// Kernel A: dual projection GEMM.
//   z==0:  g_qproj[m][h]        = queries[m][:] @ Wq[:][h]          (f32)
//   z==1:  g_kproj2[b][h/2][kj] = keys GEMM, transposed + fp16 pack
// Tiles 64x64, BK=16, 256 threads, 4x4/thread.
// ---------------------------------------------------------------------------
__global__ void __launch_bounds__(256) proj_kernel(
    const float* __restrict__ Aq, const float* __restrict__ Ak,
    const float* __restrict__ Wq, const float* __restrict__ Wk)
{
    const int z = blockIdx.z;
    const float* __restrict__ A = z ? Ak : Aq;
    const float* __restrict__ W = z ? Wk : Wq;

    __shared__ float As[16][64];   // [k][m]
    __shared__ float Ws[16][64];   // [k][n]

    const int tid = threadIdx.x;
    const int m0 = blockIdx.x * 64;
    const int n0 = blockIdx.y * 64;
    const int tx = tid & 15, ty = tid >> 4;

    const int ar = tid >> 2, ac4 = tid & 3;     // A tile: 64 rows x 16 cols
    const int wr = tid >> 4, wc4 = tid & 15;    // W tile: 16 rows x 64 cols

    float c[4][4] = {};

    for (int kk = 0; kk < 256; kk += 16) {
        float4 av = *(const float4*)&A[(m0 + ar) * 256 + kk + ac4 * 4];
        As[ac4 * 4 + 0][ar] = av.x;
        As[ac4 * 4 + 1][ar] = av.y;
        As[ac4 * 4 + 2][ar] = av.z;
        As[ac4 * 4 + 3][ar] = av.w;
        *(float4*)&Ws[wr][wc4 * 4] =
            *(const float4*)&W[(kk + wr) * 256 + n0 + wc4 * 4];
        __syncthreads();
#pragma unroll
        for (int k = 0; k < 16; k++) {
            float4 a4 = *(const float4*)&As[k][ty * 4];
            float4 b4 = *(const float4*)&Ws[k][tx * 4];
            float aa[4] = {a4.x, a4.y, a4.z, a4.w};
            float bb[4] = {b4.x, b4.y, b4.z, b4.w};
#pragma unroll
            for (int i = 0; i < 4; i++)
#pragma unroll
                for (int j = 0; j < 4; j++) c[i][j] += aa[i] * bb[j];
        }
        __syncthreads();
    }

    if (z == 0) {
#pragma unroll
        for (int i = 0; i < 4; i++) {
            int m = m0 + ty * 4 + i;
            *(float4*)&g_qproj[m * 256 + n0 + tx * 4] =
                make_float4(c[i][0], c[i][1], c[i][2], c[i][3]);
        }
    } else {
#pragma unroll
        for (int i = 0; i < 4; i++) {
            int m = m0 + ty * 4 + i;
            int b = m >> 8, kj = m & 255;
            int h = n0 + tx * 4;                 // even
            g_kproj2[(b * H2 + (h >> 1) + 0) * KN + kj] =
                __floats2half2_rn(c[i][0], c[i][1]);
            g_kproj2[(b * H2 + (h >> 1) + 1) * KN + kj] =
                __floats2half2_rn(c[i][2], c[i][3]);
        }
    }
}

// ---------------------------------------------------------------------------
// Kernel B: fused scores + mask + softmax + attn@V.
// One block per (b, 16 q-rows); thread == kj column in score phase.
// This round: occupancy 4 blocks/SM (launch_bounds regs<=64) + double-buffered
// prefetch of the k-chunk loads to hide L2 latency; AV phase MLP=8.
// ---------------------------------------------------------------------------
__global__ void __launch_bounds__(256, 4) attn_kernel(
    const float* __restrict__ values, const int* __restrict__ vlens_i32,
    const float* __restrict__ wv, float* __restrict__ out)
{
    const int b  = blockIdx.y;
    const int q0 = blockIdx.x * TQ;
    const int tid = threadIdx.x;

    __shared__ __half2 q_s2[TQ][H2];   // 8 KB   (q proj, fp16 pairs)
    __shared__ float   s_s[TQ][KN];    // 16 KB  (scores -> attn)
    __shared__ __half2 wv_s2[H2];      // 0.5 KB

    // load q tile (f32 -> half2) + wv
    const float* qbase = g_qproj + (b * QN + q0) * HN;
    for (int i = tid; i < TQ * H2; i += 256) {
        float2 v = ((const float2*)qbase)[i];
        ((__half2*)q_s2)[i] = __float22half2_rn(v);
    }
    for (int i = tid; i < H2; i += 256) {
        float2 v = ((const float2*)wv)[i];
        wv_s2[i] = __float22half2_rn(v);
    }
    __syncthreads();

    // ---- score phase: this thread owns column kj = tid ----
    const int kj = tid;
    float acc[TQ];
#pragma unroll
    for (int i = 0; i < TQ; i++) acc[i] = 0.f;

    const __half2* kbase = g_kproj2 + b * H2 * KN + kj;

    __half2 kv[4], kvn[4];
#pragma unroll
    for (int t = 0; t < 4; t++) kv[t] = __ldg(kbase + t * KN);

#pragma unroll 1
    for (int hc2 = 0; hc2 < H2; hc2 += 4) {          // 8 h-elems per chunk
        // prefetch next chunk (clamped to stay in-bounds; redundant last iter)
        const int nc = (hc2 + 4 < H2) ? hc2 + 4 : hc2;
#pragma unroll
        for (int t = 0; t < 4; t++) kvn[t] = __ldg(kbase + (nc + t) * KN);

        __half2 wr2[4];
#pragma unroll
        for (int t = 0; t < 4; t++) wr2[t] = wv_s2[hc2 + t];

#pragma unroll
        for (int qi = 0; qi < TQ; qi++) {
            uint4 qraw = *(const uint4*)&q_s2[qi][hc2];   // 4 half2 = 8 h
            __half2 q2[4];
            q2[0] = *(__half2*)&qraw.x; q2[1] = *(__half2*)&qraw.y;
            q2[2] = *(__half2*)&qraw.z; q2[3] = *(__half2*)&qraw.w;
            __half2 a = __float2half2_rn(0.f);
#pragma unroll
            for (int t = 0; t < 4; t++)
                a = __hfma2(wr2[t], htanh2(__hadd2(q2[t], kv[t])), a);
            float2 f = __half22float2(a);
            acc[qi] += f.x + f.y;
        }
#pragma unroll
        for (int t = 0; t < 4; t++) kv[t] = kvn[t];
    }

    // ---- mask + stash scores ----
    const int stride = (vlens_i32[1] == 0) ? 2 : 1;   // int64 vs int32 probe
    const int vlen = vlens_i32[b * stride];
    const bool live = (kj < vlen);
#pragma unroll
    for (int qi = 0; qi < TQ; qi++)
        s_s[qi][kj] = live ? acc[qi] : -1e6f;
    __syncthreads();

    // ---- softmax: warp w handles rows 2w, 2w+1 ----
    const int w = tid >> 5, lane = tid & 31;
#pragma unroll
    for (int rr = 0; rr < 2; rr++) {
        const int r = w * 2 + rr;
        float vals[8];
        float vmax = -1e30f;
#pragma unroll
        for (int t = 0; t < 8; t++) {
            vals[t] = s_s[r][lane + t * 32];
            vmax = fmaxf(vmax, vals[t]);
        }
#pragma unroll
        for (int off = 16; off; off >>= 1)
            vmax = fmaxf(vmax, __shfl_xor_sync(0xFFFFFFFFu, vmax, off));
        float vsum = 0.f;
#pragma unroll
        for (int t = 0; t < 8; t++) {
            vals[t] = __expf(vals[t] - vmax);
            vsum += vals[t];
        }
#pragma unroll
        for (int off = 16; off; off >>= 1)
            vsum += __shfl_xor_sync(0xFFFFFFFFu, vsum, off);
        const float inv = 1.f / vsum;
#pragma unroll
        for (int t = 0; t < 8; t++)
            s_s[r][lane + t * 32] = vals[t] * inv;
    }
    __syncthreads();

    // ---- attn @ values: thread owns output column d = tid; MLP=8 ----
    const int d = tid;
    const float* vb = values + b * KN * DN + d;
    float o[TQ];
#pragma unroll
    for (int i = 0; i < TQ; i++) o[i] = 0.f;
#pragma unroll 1
    for (int k = 0; k < KN; k += 8) {
        float v[8];
#pragma unroll
        for (int t = 0; t < 8; t++) v[t] = __ldg(vb + (k + t) * DN);
#pragma unroll
        for (int t = 0; t < 8; t++) {
#pragma unroll
            for (int qi = 0; qi < TQ; qi++) o[qi] += s_s[qi][k + t] * v[t];
        }
    }
    float* ob = out + (b * QN + q0) * DN + d;
#pragma unroll
    for (int qi = 0; qi < TQ; qi++) ob[qi * DN] = o[qi];
}

// ---------------------------------------------------------------------------
extern "C" void kernel_launch(void* const* d_in, const int* in_sizes, int n_in,
                              void* d_out, int out_size)
{
    const float* queries = (const float*)d_in[0];
    const float* keys    = (const float*)d_in[1];
    const float* values  = (const float*)d_in[2];
    const int*   vlens   = (const int*)d_in[3];
    const float* Wq      = (const float*)d_in[4];
    const float* Wk      = (const float*)d_in[5];
    const float* wv      = (const float*)d_in[6];
    float*       out     = (float*)d_out;

    dim3 gA(64, 4, 2);               // (4096/64, 256/64, {q,k})
    proj_kernel<<<gA, 256>>>(queries, keys, Wq, Wk);

    dim3 gB(QN / TQ, BN);            // (16, 16) = 256 blocks
    attn_kernel<<<gB, 256>>>(values, vlens, wv, out);
}

// round 6
// speedup vs baseline: 1.4226x; 1.3094x over previous
#include <cuda_runtime.h>
#include <cuda_fp16.h>

#define BN 16
#define QN 256
#define KN 256
#define DN 256
#define HN 256
#define TQ 8
#define H2 (HN/2)

// scratch (device globals: no allocation allowed)
__device__ float   g_qproj[BN * QN * HN];        // [b][q][h]      f32
__device__ __half2 g_kproj2[BN * H2 * KN];       // [b][h/2][kj]   half2 (h,h+1)

__device__ __forceinline__ __half2 htanh2(__half2 x) {
    unsigned r, xi = *(unsigned*)&x;
    asm("tanh.approx.f16x2 %0, %1;" : "=r"(r) : "r"(xi));
    return *(__half2*)&r;
}

// ---------------------------------------------------------------------------
// Kernel A: dual projection GEMM.
//   z==0:  g_qproj[m][h]        = queries[m][:] @ Wq[:][h]          (f32)
//   z==1:  g_kproj2[b][h/2][kj] = keys GEMM, transposed + fp16 pack
// Tiles 64x64, BK=16, 256 threads, 4x4/thread.
// ---------------------------------------------------------------------------
__global__ void __launch_bounds__(256) proj_kernel(
    const float* __restrict__ Aq, const float* __restrict__ Ak,
    const float* __restrict__ Wq, const float* __restrict__ Wk)
{
    const int z = blockIdx.z;
    const float* __restrict__ A = z ? Ak : Aq;
    const float* __restrict__ W = z ? Wk : Wq;

    __shared__ float As[16][64];   // [k][m]
    __shared__ float Ws[16][64];   // [k][n]

    const int tid = threadIdx.x;
    const int m0 = blockIdx.x * 64;
    const int n0 = blockIdx.y * 64;
    const int tx = tid & 15, ty = tid >> 4;

    const int ar = tid >> 2, ac4 = tid & 3;     // A tile: 64 rows x 16 cols
    const int wr = tid >> 4, wc4 = tid & 15;    // W tile: 16 rows x 64 cols

    float c[4][4] = {};

    for (int kk = 0; kk < 256; kk += 16) {
        float4 av = *(const float4*)&A[(m0 + ar) * 256 + kk + ac4 * 4];
        As[ac4 * 4 + 0][ar] = av.x;
        As[ac4 * 4 + 1][ar] = av.y;
        As[ac4 * 4 + 2][ar] = av.z;
        As[ac4 * 4 + 3][ar] = av.w;
        *(float4*)&Ws[wr][wc4 * 4] =
            *(const float4*)&W[(kk + wr) * 256 + n0 + wc4 * 4];
        __syncthreads();
#pragma unroll
        for (int k = 0; k < 16; k++) {
            float4 a4 = *(const float4*)&As[k][ty * 4];
            float4 b4 = *(const float4*)&Ws[k][tx * 4];
            float aa[4] = {a4.x, a4.y, a4.z, a4.w};
            float bb[4] = {b4.x, b4.y, b4.z, b4.w};
#pragma unroll
            for (int i = 0; i < 4; i++)
#pragma unroll
                for (int j = 0; j < 4; j++) c[i][j] += aa[i] * bb[j];
        }
        __syncthreads();
    }

    if (z == 0) {
#pragma unroll
        for (int i = 0; i < 4; i++) {
            int m = m0 + ty * 4 + i;
            *(float4*)&g_qproj[m * 256 + n0 + tx * 4] =
                make_float4(c[i][0], c[i][1], c[i][2], c[i][3]);
        }
    } else {
#pragma unroll
        for (int i = 0; i < 4; i++) {
            int m = m0 + ty * 4 + i;
            int b = m >> 8, kj = m & 255;
            int h = n0 + tx * 4;                 // even
            g_kproj2[(b * H2 + (h >> 1) + 0) * KN + kj] =
                __floats2half2_rn(c[i][0], c[i][1]);
            g_kproj2[(b * H2 + (h >> 1) + 1) * KN + kj] =
                __floats2half2_rn(c[i][2], c[i][3]);
        }
    }
}

// ---------------------------------------------------------------------------
// Kernel B: fused scores + mask + softmax + attn@V.
// TQ=8 -> 512 blocks (3-4 resident/SM). Masked columns (kj >= vlen) skip the
// entire score loop; AV loop bounded by vlen (masked attn weights are exactly
// 0 after softmax underflow, so skipping them is bit-equivalent).
// ---------------------------------------------------------------------------
__global__ void __launch_bounds__(256, 4) attn_kernel(
    const float* __restrict__ values, const int* __restrict__ vlens_i32,
    const float* __restrict__ wv, float* __restrict__ out)
{
    const int b  = blockIdx.y;
    const int q0 = blockIdx.x * TQ;
    const int tid = threadIdx.x;

    __shared__ __half2 q_s2[TQ][H2];   // 4 KB   (q proj, fp16 pairs)
    __shared__ float   s_s[TQ][KN];    // 8 KB   (scores -> attn)
    __shared__ __half2 wv_s2[H2];      // 0.5 KB

    // load q tile (f32 -> half2) + wv
    const float* qbase = g_qproj + (b * QN + q0) * HN;
    for (int i = tid; i < TQ * H2; i += 256) {
        float2 v = ((const float2*)qbase)[i];
        ((__half2*)q_s2)[i] = __float22half2_rn(v);
    }
    for (int i = tid; i < H2; i += 256) {
        float2 v = ((const float2*)wv)[i];
        wv_s2[i] = __float22half2_rn(v);
    }
    __syncthreads();

    const int stride = (vlens_i32[1] == 0) ? 2 : 1;   // int64 vs int32 probe
    const int vlen = vlens_i32[b * stride];

    // ---- score phase: this thread owns column kj = tid ----
    const int kj = tid;
    float acc[TQ];
#pragma unroll
    for (int i = 0; i < TQ; i++) acc[i] = 0.f;

    if (kj < vlen) {                   // masked columns skip all score work
        const __half2* kbase = g_kproj2 + b * H2 * KN + kj;

        __half2 kv[4], kvn[4];
#pragma unroll
        for (int t = 0; t < 4; t++) kv[t] = __ldg(kbase + t * KN);

#pragma unroll 1
        for (int hc2 = 0; hc2 < H2; hc2 += 4) {      // 8 h-elems per chunk
            const int nc = (hc2 + 4 < H2) ? hc2 + 4 : hc2;
#pragma unroll
            for (int t = 0; t < 4; t++) kvn[t] = __ldg(kbase + (nc + t) * KN);

            __half2 wr2[4];
#pragma unroll
            for (int t = 0; t < 4; t++) wr2[t] = wv_s2[hc2 + t];

#pragma unroll
            for (int qi = 0; qi < TQ; qi++) {
                uint4 qraw = *(const uint4*)&q_s2[qi][hc2];   // 4 half2 = 8 h
                __half2 q2[4];
                q2[0] = *(__half2*)&qraw.x; q2[1] = *(__half2*)&qraw.y;
                q2[2] = *(__half2*)&qraw.z; q2[3] = *(__half2*)&qraw.w;
                __half2 a = __float2half2_rn(0.f);
#pragma unroll
                for (int t = 0; t < 4; t++)
                    a = __hfma2(wr2[t], htanh2(__hadd2(q2[t], kv[t])), a);
                float2 f = __half22float2(a);
                acc[qi] += f.x + f.y;
            }
#pragma unroll
            for (int t = 0; t < 4; t++) kv[t] = kvn[t];
        }
    }

    // ---- mask + stash scores ----
    const bool live = (kj < vlen);
#pragma unroll
    for (int qi = 0; qi < TQ; qi++)
        s_s[qi][kj] = live ? acc[qi] : -1e6f;
    __syncthreads();

    // ---- softmax: warp w handles row w ----
    const int w = tid >> 5, lane = tid & 31;
    {
        const int r = w;
        float vals[8];
        float vmax = -1e30f;
#pragma unroll
        for (int t = 0; t < 8; t++) {
            vals[t] = s_s[r][lane + t * 32];
            vmax = fmaxf(vmax, vals[t]);
        }
#pragma unroll
        for (int off = 16; off; off >>= 1)
            vmax = fmaxf(vmax, __shfl_xor_sync(0xFFFFFFFFu, vmax, off));
        float vsum = 0.f;
#pragma unroll
        for (int t = 0; t < 8; t++) {
            vals[t] = __expf(vals[t] - vmax);
            vsum += vals[t];
        }
#pragma unroll
        for (int off = 16; off; off >>= 1)
            vsum += __shfl_xor_sync(0xFFFFFFFFu, vsum, off);
        const float inv = 1.f / vsum;
#pragma unroll
        for (int t = 0; t < 8; t++)
            s_s[r][lane + t * 32] = vals[t] * inv;
    }
    __syncthreads();

    // ---- attn @ values: thread owns output column d = tid; MLP=8 ----
    // k >= vlen has attn == 0 exactly -> loop only to vlen rounded up to 8.
    const int d = tid;
    const int kend = (vlen + 7) & ~7;
    const float* vb = values + b * KN * DN + d;
    float o[TQ];
#pragma unroll
    for (int i = 0; i < TQ; i++) o[i] = 0.f;
#pragma unroll 1
    for (int k = 0; k < kend; k += 8) {
        float v[8];
#pragma unroll
        for (int t = 0; t < 8; t++) v[t] = __ldg(vb + (k + t) * DN);
#pragma unroll
        for (int t = 0; t < 8; t++) {
#pragma unroll
            for (int qi = 0; qi < TQ; qi++) o[qi] += s_s[qi][k + t] * v[t];
        }
    }
    float* ob = out + (b * QN + q0) * DN + d;
#pragma unroll
    for (int qi = 0; qi < TQ; qi++) ob[qi * DN] = o[qi];
}

// ---------------------------------------------------------------------------
extern "C" void kernel_launch(void* const* d_in, const int* in_sizes, int n_in,
                              void* d_out, int out_size)
{
    const float* queries = (const float*)d_in[0];
    const float* keys    = (const float*)d_in[1];
    const float* values  = (const float*)d_in[2];
    const int*   vlens   = (const int*)d_in[3];
    const float* Wq      = (const float*)d_in[4];
    const float* Wk      = (const float*)d_in[5];
    const float* wv      = (const float*)d_in[6];
    float*       out     = (float*)d_out;

    dim3 gA(64, 4, 2);               // (4096/64, 256/64, {q,k})
    proj_kernel<<<gA, 256>>>(queries, keys, Wq, Wk);

    dim3 gB(QN / TQ, BN);            // (32, 16) = 512 blocks
    attn_kernel<<<gB, 256>>>(values, vlens, wv, out);
}

// round 7
// speedup vs baseline: 1.4528x; 1.0212x over previous
#include <cuda_runtime.h>
#include <cuda_fp16.h>

#define BN 16
#define QN 256
#define KN 256
#define DN 256
#define HN 256
#define TQ 8
#define H2 (HN/2)

// scratch (device globals: no allocation allowed)
__device__ float   g_qproj[BN * QN * HN];        // [b][q][h]       f32
__device__ __half2 g_kproj2[BN * KN * H2];       // [b][kj][h/2]    half2 (h,h+1)

__device__ __forceinline__ __half2 htanh2(__half2 x) {
    unsigned r, xi = *(unsigned*)&x;
    asm("tanh.approx.f16x2 %0, %1;" : "=r"(r) : "r"(xi));
    return *(__half2*)&r;
}

// ---------------------------------------------------------------------------
// Kernel A: dual projection GEMM.
//   z==0:  g_qproj[m][h]          = queries[m][:] @ Wq[:][h]        (f32)
//   z==1:  g_kproj2[b][kj][h/2]   = keys GEMM, fp16 pack, kj-major rows
// Tiles 64x64, BK=16, 256 threads, 4x4/thread.
// ---------------------------------------------------------------------------
__global__ void __launch_bounds__(256) proj_kernel(
    const float* __restrict__ Aq, const float* __restrict__ Ak,
    const float* __restrict__ Wq, const float* __restrict__ Wk)
{
    const int z = blockIdx.z;
    const float* __restrict__ A = z ? Ak : Aq;
    const float* __restrict__ W = z ? Wk : Wq;

    __shared__ float As[16][64];   // [k][m]
    __shared__ float Ws[16][64];   // [k][n]

    const int tid = threadIdx.x;
    const int m0 = blockIdx.x * 64;
    const int n0 = blockIdx.y * 64;
    const int tx = tid & 15, ty = tid >> 4;

    const int ar = tid >> 2, ac4 = tid & 3;     // A tile: 64 rows x 16 cols
    const int wr = tid >> 4, wc4 = tid & 15;    // W tile: 16 rows x 64 cols

    float c[4][4] = {};

    for (int kk = 0; kk < 256; kk += 16) {
        float4 av = *(const float4*)&A[(m0 + ar) * 256 + kk + ac4 * 4];
        As[ac4 * 4 + 0][ar] = av.x;
        As[ac4 * 4 + 1][ar] = av.y;
        As[ac4 * 4 + 2][ar] = av.z;
        As[ac4 * 4 + 3][ar] = av.w;
        *(float4*)&Ws[wr][wc4 * 4] =
            *(const float4*)&W[(kk + wr) * 256 + n0 + wc4 * 4];
        __syncthreads();
#pragma unroll
        for (int k = 0; k < 16; k++) {
            float4 a4 = *(const float4*)&As[k][ty * 4];
            float4 b4 = *(const float4*)&Ws[k][tx * 4];
            float aa[4] = {a4.x, a4.y, a4.z, a4.w};
            float bb[4] = {b4.x, b4.y, b4.z, b4.w};
#pragma unroll
            for (int i = 0; i < 4; i++)
#pragma unroll
                for (int j = 0; j < 4; j++) c[i][j] += aa[i] * bb[j];
        }
        __syncthreads();
    }

    if (z == 0) {
#pragma unroll
        for (int i = 0; i < 4; i++) {
            int m = m0 + ty * 4 + i;
            *(float4*)&g_qproj[m * 256 + n0 + tx * 4] =
                make_float4(c[i][0], c[i][1], c[i][2], c[i][3]);
        }
    } else {
#pragma unroll
        for (int i = 0; i < 4; i++) {
            int m = m0 + ty * 4 + i;
            int b = m >> 8, kj = m & 255;
            int h = n0 + tx * 4;                 // even
            __half2* row = g_kproj2 + (b * KN + kj) * H2 + (h >> 1);
            row[0] = __floats2half2_rn(c[i][0], c[i][1]);
            row[1] = __floats2half2_rn(c[i][2], c[i][3]);
        }
    }
}

// ---------------------------------------------------------------------------
// Kernel B: fused scores + mask + softmax + attn@V.
// TQ=8 -> 512 blocks. Masked columns skip score work; AV bounded by vlen.
// This round: k column contiguous per thread (LDG.128 streams, mostly L1
// hits), prefetch distance 2, AV double-buffered.
// ---------------------------------------------------------------------------
__global__ void __launch_bounds__(256, 4) attn_kernel(
    const float* __restrict__ values, const int* __restrict__ vlens_i32,
    const float* __restrict__ wv, float* __restrict__ out)
{
    const int b  = blockIdx.y;
    const int q0 = blockIdx.x * TQ;
    const int tid = threadIdx.x;

    __shared__ __half2 q_s2[TQ][H2];   // 4 KB   (q proj, fp16 pairs)
    __shared__ float   s_s[TQ][KN];    // 8 KB   (scores -> attn)
    __shared__ __half2 wv_s2[H2];      // 0.5 KB

    // load q tile (f32 -> half2) + wv
    const float* qbase = g_qproj + (b * QN + q0) * HN;
    for (int i = tid; i < TQ * H2; i += 256) {
        float2 v = ((const float2*)qbase)[i];
        ((__half2*)q_s2)[i] = __float22half2_rn(v);
    }
    for (int i = tid; i < H2; i += 256) {
        float2 v = ((const float2*)wv)[i];
        wv_s2[i] = __float22half2_rn(v);
    }
    __syncthreads();

    const int stride = (vlens_i32[1] == 0) ? 2 : 1;   // int64 vs int32 probe
    const int vlen = vlens_i32[b * stride];

    // ---- score phase: this thread owns column kj = tid ----
    const int kj = tid;
    float acc[TQ];
#pragma unroll
    for (int i = 0; i < TQ; i++) acc[i] = 0.f;

    if (kj < vlen) {                   // masked columns skip all score work
        // contiguous 512B row for this column: [b][kj][h/2]
        const uint4* krow = (const uint4*)(g_kproj2 + (b * KN + kj) * H2);

        uint4 kc0 = __ldg(krow + 0);   // chunk i   (4 half2 = 8 h)
        uint4 kc1 = __ldg(krow + 1);   // chunk i+1

#pragma unroll 1
        for (int c = 0; c < 32; c++) {             // 32 chunks of 8 h
            const int pf = (c + 2 < 32) ? c + 2 : c;
            uint4 kc2 = __ldg(krow + pf);          // prefetch distance 2

            __half2 kv2[4];
            kv2[0] = *(__half2*)&kc0.x; kv2[1] = *(__half2*)&kc0.y;
            kv2[2] = *(__half2*)&kc0.z; kv2[3] = *(__half2*)&kc0.w;

            const int hc2 = c * 4;
            __half2 wr2[4];
#pragma unroll
            for (int t = 0; t < 4; t++) wr2[t] = wv_s2[hc2 + t];

#pragma unroll
            for (int qi = 0; qi < TQ; qi++) {
                uint4 qraw = *(const uint4*)&q_s2[qi][hc2];   // 4 half2 = 8 h
                __half2 q2[4];
                q2[0] = *(__half2*)&qraw.x; q2[1] = *(__half2*)&qraw.y;
                q2[2] = *(__half2*)&qraw.z; q2[3] = *(__half2*)&qraw.w;
                __half2 a = __float2half2_rn(0.f);
#pragma unroll
                for (int t = 0; t < 4; t++)
                    a = __hfma2(wr2[t], htanh2(__hadd2(q2[t], kv2[t])), a);
                float2 f = __half22float2(a);
                acc[qi] += f.x + f.y;
            }
            kc0 = kc1;
            kc1 = kc2;
        }
    }

    // ---- mask + stash scores ----
    const bool live = (kj < vlen);
#pragma unroll
    for (int qi = 0; qi < TQ; qi++)
        s_s[qi][kj] = live ? acc[qi] : -1e6f;
    __syncthreads();

    // ---- softmax: warp w handles row w ----
    const int w = tid >> 5, lane = tid & 31;
    {
        const int r = w;
        float vals[8];
        float vmax = -1e30f;
#pragma unroll
        for (int t = 0; t < 8; t++) {
            vals[t] = s_s[r][lane + t * 32];
            vmax = fmaxf(vmax, vals[t]);
        }
#pragma unroll
        for (int off = 16; off; off >>= 1)
            vmax = fmaxf(vmax, __shfl_xor_sync(0xFFFFFFFFu, vmax, off));
        float vsum = 0.f;
#pragma unroll
        for (int t = 0; t < 8; t++) {
            vals[t] = __expf(vals[t] - vmax);
            vsum += vals[t];
        }
#pragma unroll
        for (int off = 16; off; off >>= 1)
            vsum += __shfl_xor_sync(0xFFFFFFFFu, vsum, off);
        const float inv = 1.f / vsum;
#pragma unroll
        for (int t = 0; t < 8; t++)
            s_s[r][lane + t * 32] = vals[t] * inv;
    }
    __syncthreads();

    // ---- attn @ values: thread owns column d = tid; double-buffered MLP=8 ----
    // k >= vlen has attn == 0 exactly -> loop only to vlen rounded up to 8.
    const int d = tid;
    const int kend = (vlen + 7) & ~7;              // vlen >= 1 so kend >= 8
    const float* vb = values + b * KN * DN + d;
    float o[TQ];
#pragma unroll
    for (int i = 0; i < TQ; i++) o[i] = 0.f;

    float v[8], vn[8];
#pragma unroll
    for (int t = 0; t < 8; t++) v[t] = __ldg(vb + t * DN);

#pragma unroll 1
    for (int k = 0; k < kend; k += 8) {
        const int nk = (k + 8 < kend) ? k + 8 : k;
#pragma unroll
        for (int t = 0; t < 8; t++) vn[t] = __ldg(vb + (nk + t) * DN);
#pragma unroll
        for (int t = 0; t < 8; t++) {
#pragma unroll
            for (int qi = 0; qi < TQ; qi++) o[qi] += s_s[qi][k + t] * v[t];
        }
#pragma unroll
        for (int t = 0; t < 8; t++) v[t] = vn[t];
    }
    float* ob = out + (b * QN + q0) * DN + d;
#pragma unroll
    for (int qi = 0; qi < TQ; qi++) ob[qi * DN] = o[qi];
}

// ---------------------------------------------------------------------------
extern "C" void kernel_launch(void* const* d_in, const int* in_sizes, int n_in,
                              void* d_out, int out_size)
{
    const float* queries = (const float*)d_in[0];
    const float* keys    = (const float*)d_in[1];
    const float* values  = (const float*)d_in[2];
    const int*   vlens   = (const int*)d_in[3];
    const float* Wq      = (const float*)d_in[4];
    const float* Wk      = (const float*)d_in[5];
    const float* wv      = (const float*)d_in[6];
    float*       out     = (float*)d_out;

    dim3 gA(64, 4, 2);               // (4096/64, 256/64, {q,k})
    proj_kernel<<<gA, 256>>>(queries, keys, Wq, Wk);

    dim3 gB(QN / TQ, BN);            // (32, 16) = 512 blocks
    attn_kernel<<<gB, 256>>>(values, vlens, wv, out);
}

// round 8
// speedup vs baseline: 1.8236x; 1.2553x over previous
#include <cuda_runtime.h>
#include <cuda_fp16.h>
#include <cstdint>

#define BN 16
#define QN 256
#define KN 256
#define DN 256
#define HN 256
#define TQ 8
#define H2 (HN/2)

// scratch (device globals: no allocation allowed) — both projections now half,
// row-major [row][h] with h contiguous (q row = (b,q), k row = (b,kj)).
__device__ __half g_qproj[BN * QN * HN];
__device__ __half g_kproj[BN * KN * HN];

__device__ __forceinline__ __half2 htanh2(__half2 x) {
    unsigned r, xi = *(unsigned*)&x;
    asm("tanh.approx.f16x2 %0, %1;" : "=r"(r) : "r"(xi));
    return *(__half2*)&r;
}

// ---------------------------------------------------------------------------
// Kernel A: dual projection GEMM on tensor cores (m16n8k16 f16, f32 accum).
//   z==0: g_qproj[m][h] = queries[m][:] @ Wq[:][h]
//   z==1: g_kproj[m][h] = keys[m][:]    @ Wk[:][h]
// Block tile 128x128, 8 warps of 32x64. Inputs cvt f32->f16 on the fly.
// A smem [row][k] stride 24 halfs (48B, conflict-free ldmatrix);
// B smem stored transposed [n][k] stride 24.
// ---------------------------------------------------------------------------
__global__ void __launch_bounds__(256, 1) proj_kernel(
    const float* __restrict__ Aq, const float* __restrict__ Ak,
    const float* __restrict__ Wq, const float* __restrict__ Wk)
{
    const int z = blockIdx.z;
    const float* __restrict__ A = z ? Ak : Aq;
    const float* __restrict__ W = z ? Wk : Wq;
    __half* __restrict__ out = z ? g_kproj : g_qproj;

    __shared__ __half As[128 * 24];   // [row][k] stride 24
    __shared__ __half Bs[128 * 24];   // [n][k]   stride 24 (transposed W tile)

    const int tid  = threadIdx.x;
    const int wid  = tid >> 5, lane = tid & 31;
    const int m0   = blockIdx.x * 128;
    const int n0   = blockIdx.y * 128;
    const int wm   = (wid & 3) * 32;      // warp rows within tile
    const int wn   = (wid >> 2) * 64;     // warp cols within tile

    // loader mapping
    const int arow = tid >> 1, acol = (tid & 1) * 8;   // A: 128 rows x 16 k
    const int bk   = tid >> 4, bn   = (tid & 15) * 8;  // W: 16 k x 128 n

    const uint32_t as_base = (uint32_t)__cvta_generic_to_shared(As);
    const uint32_t bs_base = (uint32_t)__cvta_generic_to_shared(Bs);

    // preload k-step 0
    float4 a0v = *(const float4*)&A[(m0 + arow) * 256 + acol];
    float4 a1v = *(const float4*)&A[(m0 + arow) * 256 + acol + 4];
    float4 b0v = *(const float4*)&W[bk * 256 + n0 + bn];
    float4 b1v = *(const float4*)&W[bk * 256 + n0 + bn + 4];

    float acc[2][8][4];
#pragma unroll
    for (int mi = 0; mi < 2; mi++)
#pragma unroll
        for (int ni = 0; ni < 8; ni++)
#pragma unroll
            for (int t = 0; t < 4; t++) acc[mi][ni][t] = 0.f;

#pragma unroll 1
    for (int ks = 0; ks < 16; ks++) {
        // store current regs to smem (with f32->f16 cvt)
        {
            __half2 ah[4];
            ah[0] = __floats2half2_rn(a0v.x, a0v.y);
            ah[1] = __floats2half2_rn(a0v.z, a0v.w);
            ah[2] = __floats2half2_rn(a1v.x, a1v.y);
            ah[3] = __floats2half2_rn(a1v.z, a1v.w);
            *(uint4*)&As[arow * 24 + acol] = *(uint4*)ah;

            float bf[8] = {b0v.x, b0v.y, b0v.z, b0v.w,
                           b1v.x, b1v.y, b1v.z, b1v.w};
#pragma unroll
            for (int j = 0; j < 8; j++)
                Bs[(bn + j) * 24 + bk] = __float2half_rn(bf[j]);
        }
        __syncthreads();

        // prefetch next k-step (overlaps with ldmatrix+mma below)
        if (ks < 15) {
            const int kk = (ks + 1) * 16;
            a0v = *(const float4*)&A[(m0 + arow) * 256 + kk + acol];
            a1v = *(const float4*)&A[(m0 + arow) * 256 + kk + acol + 4];
            b0v = *(const float4*)&W[(kk + bk) * 256 + n0 + bn];
            b1v = *(const float4*)&W[(kk + bk) * 256 + n0 + bn + 4];
        }

        // A fragments: 2 x ldmatrix.x4
        uint32_t af[2][4];
#pragma unroll
        for (int mi = 0; mi < 2; mi++) {
            uint32_t addr = as_base +
                ((wm + mi * 16 + (lane & 15)) * 24 + (lane >> 4) * 8) * 2;
            asm volatile(
                "ldmatrix.sync.aligned.m8n8.x4.shared.b16 {%0,%1,%2,%3}, [%4];"
                : "=r"(af[mi][0]), "=r"(af[mi][1]),
                  "=r"(af[mi][2]), "=r"(af[mi][3]) : "r"(addr));
        }
        // B fragments: 4 x ldmatrix.x4 covering 8 n-octets
        uint32_t bf[8][2];
#pragma unroll
        for (int g = 0; g < 4; g++) {
            uint32_t addr = bs_base +
                ((wn + g * 16 + ((lane >> 4) << 3) + (lane & 7)) * 24 +
                 ((lane >> 3) & 1) * 8) * 2;
            uint32_t r0, r1, r2, r3;
            asm volatile(
                "ldmatrix.sync.aligned.m8n8.x4.shared.b16 {%0,%1,%2,%3}, [%4];"
                : "=r"(r0), "=r"(r1), "=r"(r2), "=r"(r3) : "r"(addr));
            bf[g * 2 + 0][0] = r0; bf[g * 2 + 0][1] = r1;
            bf[g * 2 + 1][0] = r2; bf[g * 2 + 1][1] = r3;
        }
#pragma unroll
        for (int mi = 0; mi < 2; mi++)
#pragma unroll
            for (int ni = 0; ni < 8; ni++) {
                asm volatile(
                    "mma.sync.aligned.m16n8k16.row.col.f32.f16.f16.f32 "
                    "{%0,%1,%2,%3}, {%4,%5,%6,%7}, {%8,%9}, {%0,%1,%2,%3};"
                    : "+f"(acc[mi][ni][0]), "+f"(acc[mi][ni][1]),
                      "+f"(acc[mi][ni][2]), "+f"(acc[mi][ni][3])
                    : "r"(af[mi][0]), "r"(af[mi][1]),
                      "r"(af[mi][2]), "r"(af[mi][3]),
                      "r"(bf[ni][0]), "r"(bf[ni][1]));
            }
        __syncthreads();
    }

    // epilogue: c frag (row=lane>>2, col=(lane&3)*2; +8 row for c2,c3)
#pragma unroll
    for (int mi = 0; mi < 2; mi++)
#pragma unroll
        for (int ni = 0; ni < 8; ni++) {
            const int row = m0 + wm + mi * 16 + (lane >> 2);
            const int col = n0 + wn + ni * 8 + (lane & 3) * 2;
            *(__half2*)&out[row * 256 + col] =
                __floats2half2_rn(acc[mi][ni][0], acc[mi][ni][1]);
            *(__half2*)&out[(row + 8) * 256 + col] =
                __floats2half2_rn(acc[mi][ni][2], acc[mi][ni][3]);
        }
}

// ---------------------------------------------------------------------------
// Kernel B: fused scores + mask + softmax + attn@V.  (unchanged structure;
// q now read directly as half2 from g_qproj)
// ---------------------------------------------------------------------------
__global__ void __launch_bounds__(256, 4) attn_kernel(
    const float* __restrict__ values, const int* __restrict__ vlens_i32,
    const float* __restrict__ wv, float* __restrict__ out)
{
    const int b  = blockIdx.y;
    const int q0 = blockIdx.x * TQ;
    const int tid = threadIdx.x;

    __shared__ __half2 q_s2[TQ][H2];   // 4 KB
    __shared__ float   s_s[TQ][KN];    // 8 KB
    __shared__ __half2 wv_s2[H2];      // 0.5 KB

    // load q tile (already half) + wv
    const uint4* qbase = (const uint4*)(g_qproj + (b * QN + q0) * HN);
    for (int i = tid; i < TQ * H2 / 4; i += 256)
        ((uint4*)q_s2)[i] = qbase[i];
    for (int i = tid; i < H2; i += 256) {
        float2 v = ((const float2*)wv)[i];
        wv_s2[i] = __float22half2_rn(v);
    }
    __syncthreads();

    const int stride = (vlens_i32[1] == 0) ? 2 : 1;   // int64 vs int32 probe
    const int vlen = vlens_i32[b * stride];

    // ---- score phase: this thread owns column kj = tid ----
    const int kj = tid;
    float acc[TQ];
#pragma unroll
    for (int i = 0; i < TQ; i++) acc[i] = 0.f;

    if (kj < vlen) {
        const uint4* krow = (const uint4*)(g_kproj + (b * KN + kj) * HN);

        uint4 kc0 = __ldg(krow + 0);
        uint4 kc1 = __ldg(krow + 1);

#pragma unroll 1
        for (int c = 0; c < 32; c++) {             // 32 chunks of 8 h
            const int pf = (c + 2 < 32) ? c + 2 : c;
            uint4 kc2 = __ldg(krow + pf);

            __half2 kv2[4];
            kv2[0] = *(__half2*)&kc0.x; kv2[1] = *(__half2*)&kc0.y;
            kv2[2] = *(__half2*)&kc0.z; kv2[3] = *(__half2*)&kc0.w;

            const int hc2 = c * 4;
            __half2 wr2[4];
#pragma unroll
            for (int t = 0; t < 4; t++) wr2[t] = wv_s2[hc2 + t];

#pragma unroll
            for (int qi = 0; qi < TQ; qi++) {
                uint4 qraw = *(const uint4*)&q_s2[qi][hc2];
                __half2 q2[4];
                q2[0] = *(__half2*)&qraw.x; q2[1] = *(__half2*)&qraw.y;
                q2[2] = *(__half2*)&qraw.z; q2[3] = *(__half2*)&qraw.w;
                __half2 a = __float2half2_rn(0.f);
#pragma unroll
                for (int t = 0; t < 4; t++)
                    a = __hfma2(wr2[t], htanh2(__hadd2(q2[t], kv2[t])), a);
                float2 f = __half22float2(a);
                acc[qi] += f.x + f.y;
            }
            kc0 = kc1;
            kc1 = kc2;
        }
    }

    // ---- mask + stash scores ----
    const bool live = (kj < vlen);
#pragma unroll
    for (int qi = 0; qi < TQ; qi++)
        s_s[qi][kj] = live ? acc[qi] : -1e6f;
    __syncthreads();

    // ---- softmax: warp w handles row w ----
    const int w = tid >> 5, lane = tid & 31;
    {
        const int r = w;
        float vals[8];
        float vmax = -1e30f;
#pragma unroll
        for (int t = 0; t < 8; t++) {
            vals[t] = s_s[r][lane + t * 32];
            vmax = fmaxf(vmax, vals[t]);
        }
#pragma unroll
        for (int off = 16; off; off >>= 1)
            vmax = fmaxf(vmax, __shfl_xor_sync(0xFFFFFFFFu, vmax, off));
        float vsum = 0.f;
#pragma unroll
        for (int t = 0; t < 8; t++) {
            vals[t] = __expf(vals[t] - vmax);
            vsum += vals[t];
        }
#pragma unroll
        for (int off = 16; off; off >>= 1)
            vsum += __shfl_xor_sync(0xFFFFFFFFu, vsum, off);
        const float inv = 1.f / vsum;
#pragma unroll
        for (int t = 0; t < 8; t++)
            s_s[r][lane + t * 32] = vals[t] * inv;
    }
    __syncthreads();

    // ---- attn @ values: thread owns column d = tid; double-buffered MLP=8 ----
    const int d = tid;
    const int kend = (vlen + 7) & ~7;              // vlen >= 1 so kend >= 8
    const float* vb = values + b * KN * DN + d;
    float o[TQ];
#pragma unroll
    for (int i = 0; i < TQ; i++) o[i] = 0.f;

    float v[8], vn[8];
#pragma unroll
    for (int t = 0; t < 8; t++) v[t] = __ldg(vb + t * DN);

#pragma unroll 1
    for (int k = 0; k < kend; k += 8) {
        const int nk = (k + 8 < kend) ? k + 8 : k;
#pragma unroll
        for (int t = 0; t < 8; t++) vn[t] = __ldg(vb + (nk + t) * DN);
#pragma unroll
        for (int t = 0; t < 8; t++) {
#pragma unroll
            for (int qi = 0; qi < TQ; qi++) o[qi] += s_s[qi][k + t] * v[t];
        }
#pragma unroll
        for (int t = 0; t < 8; t++) v[t] = vn[t];
    }
    float* ob = out + (b * QN + q0) * DN + d;
#pragma unroll
    for (int qi = 0; qi < TQ; qi++) ob[qi * DN] = o[qi];
}

// ---------------------------------------------------------------------------
extern "C" void kernel_launch(void* const* d_in, const int* in_sizes, int n_in,
                              void* d_out, int out_size)
{
    const float* queries = (const float*)d_in[0];
    const float* keys    = (const float*)d_in[1];
    const float* values  = (const float*)d_in[2];
    const int*   vlens   = (const int*)d_in[3];
    const float* Wq      = (const float*)d_in[4];
    const float* Wk      = (const float*)d_in[5];
    const float* wv      = (const float*)d_in[6];
    float*       out     = (float*)d_out;

    dim3 gA(32, 2, 2);               // (4096/128, 256/128, {q,k}) = 128 blocks
    proj_kernel<<<gA, 256>>>(queries, keys, Wq, Wk);

    dim3 gB(QN / TQ, BN);            // (32, 16) = 512 blocks
    attn_kernel<<<gB, 256>>>(values, vlens, wv, out);
}